// round 2
// baseline (speedup 1.0000x reference)
#include <cuda_runtime.h>
#include <math.h>

// Problem constants (fixed shapes)
#define NE      800000
#define NNODES  50000
#define F       64
#define ZD      192
#define HID     14
#define NT      128     // combined outputs (f || s)
#define MT      64      // edges per tile in K1
#define ZR_STRIDE 196   // 192 + 4 pad floats
#define NTILES  (NE / MT)   // 12500
#define K1_GRID 148

// Scratch: combined weights, k-pair interleaved: g_wc[k2*256 + c*2 + p] = W[2*k2+p][c]
// c<64 -> lin_f col, c>=64 -> lin_s col
__device__ float g_wc[ZD * NT];

// ---------------------------------------------------------------------------
// helpers: packed f32x2 FMA (FFMA2) + unpack
// ---------------------------------------------------------------------------
__device__ __forceinline__ void ffma2(unsigned long long& d,
                                      unsigned long long a,
                                      unsigned long long b) {
    asm("fma.rn.f32x2 %0, %1, %2, %0;" : "+l"(d) : "l"(a), "l"(b));
}
__device__ __forceinline__ float lo32(unsigned long long v) {
    return __uint_as_float((unsigned)(v & 0xffffffffull));
}
__device__ __forceinline__ float hi32(unsigned long long v) {
    return __uint_as_float((unsigned)(v >> 32));
}

// ---------------------------------------------------------------------------
// K0: atom_out = atom_fea; build g_wc (k-pair-interleaved combined weights)
// ---------------------------------------------------------------------------
__global__ void k0_prep(const float* __restrict__ atom,
                        const float* __restrict__ wf,
                        const float* __restrict__ ws_,
                        float* __restrict__ atom_out)
{
    int i = blockIdx.x * blockDim.x + threadIdx.x;
    const int n4 = NNODES * F / 4;
    if (i < n4) {
        ((float4*)atom_out)[i] = ((const float4*)atom)[i];
    }
    if (i < ZD * NT) {
        int p  = i & 1;
        int c  = (i >> 1) & 127;
        int k2 = i >> 8;
        int k  = 2 * k2 + p;
        g_wc[i] = (c < 64) ? wf[c * ZD + k] : ws_[(c - 64) * ZD + k];
    }
}

// ---------------------------------------------------------------------------
// K1 gather: stage one tile's z rows [dst | src | edge_fea] into shared.
// Indices read straight from global (L1-resident); dst/decay cached in smem
// for the epilogue.
// ---------------------------------------------------------------------------
__device__ __forceinline__ void k1_gather(
    int tile, const int* __restrict__ eidx, const float* __restrict__ atom,
    const float* __restrict__ efea, const float* __restrict__ dist,
    float* zbuf, int* sdstb, float* sdecb, int tid)
{
    const int e0 = tile * MT;
    if (tid < MT) {
        int e = e0 + tid;
        sdstb[tid] = eidx[NE + e];
        float d = dist[e];
        sdecb[tid] = __expf(-d * d * (1.0f / 18.0f));
    }
    #pragma unroll
    for (int r = 0; r < 12; r++) {
        int idx = tid + r * 256;     // < 3072 = 64 edges * 48 float4
        int el  = idx / 48;
        int k4  = idx % 48;
        int e   = e0 + el;
        float4 v;
        if (k4 < 16) {
            v = ((const float4*)(atom + (size_t)eidx[NE + e] * F))[k4];
        } else if (k4 < 32) {
            v = ((const float4*)(atom + (size_t)eidx[e] * F))[k4 - 16];
        } else {
            v = ((const float4*)(efea + (size_t)e * F))[k4 - 32];
        }
        *((float4*)(zbuf + el * ZR_STRIDE) + k4) = v;
    }
}

// ---------------------------------------------------------------------------
// K1: persistent message GEMM. Per tile: 64 edges x 128 outs x K=192,
// FFMA2 mainloop (k-parity pairs), gated activation + gaussian decay,
// red.global.add.v4.f32 scatter into atom_out.
// ---------------------------------------------------------------------------
__global__ void __launch_bounds__(256)
k1_msg(const float* __restrict__ atom,
       const int*   __restrict__ eidx,
       const float* __restrict__ efea,
       const float* __restrict__ dist,
       const float* __restrict__ bf,
       const float* __restrict__ bs,
       float* __restrict__ atom_out)
{
    extern __shared__ float sm[];
    float* ws    = sm;                          // 24576 floats (interleaved weights)
    float* zr0   = ws + ZD * NT;                // 64*196
    float* zr1   = zr0 + MT * ZR_STRIDE;        // 64*196
    float* sbias = zr1 + MT * ZR_STRIDE;        // 128
    float* sdec  = sbias + NT;                  // 2*64
    int*   sdst  = (int*)(sdec + 2 * MT);       // 2*64

    const int tid = threadIdx.x;

    // stage weights once per block (coalesced, L2-resident source)
    {
        const float4* wg4 = (const float4*)g_wc;
        float4* ws4 = (float4*)ws;
        #pragma unroll
        for (int i = 0; i < 24; i++)
            ws4[tid + i * 256] = wg4[tid + i * 256];
    }
    if (tid < 64)       sbias[tid] = bf[tid];
    else if (tid < 128) sbias[tid] = bs[tid - 64];

    const int t0 = blockIdx.x;
    k1_gather(t0, eidx, atom, efea, dist, zr0, sdst, sdec, tid);
    __syncthreads();

    const int tx = tid & 15;       // 16 col-groups (4 f-cols + 4 s-cols each)
    const int ty = tid >> 4;       // 16 row-groups (4 edges each)
    const int cb = tx * 4;
    int buf = 0;

    for (int t = t0; t < NTILES; t += K1_GRID) {
        int tn = t + K1_GRID;
        if (tn < NTILES)
            k1_gather(tn, eidx, atom, efea, dist,
                      buf ? zr0 : zr1,
                      sdst + ((buf ^ 1) * MT), sdec + ((buf ^ 1) * MT), tid);

        const float* zb = (buf ? zr1 : zr0) + (ty * 4) * ZR_STRIDE;
        const int*   sdstb = sdst + buf * MT;
        const float* sdecb = sdec + buf * MT;

        unsigned long long acc[4][8];
        #pragma unroll
        for (int i = 0; i < 4; i++)
            #pragma unroll
            for (int j = 0; j < 8; j++) acc[i][j] = 0ull;

        #pragma unroll 4
        for (int k2 = 0; k2 < ZD / 2; k2++) {
            const ulonglong2* wrow = (const ulonglong2*)(ws + k2 * 256);
            ulonglong2 bf01 = wrow[tx * 2];          // col pairs cb, cb+1
            ulonglong2 bf23 = wrow[tx * 2 + 1];      // cb+2, cb+3
            ulonglong2 bs01 = wrow[32 + tx * 2];     // s-cols cb, cb+1
            ulonglong2 bs23 = wrow[32 + tx * 2 + 1]; // s-cols cb+2, cb+3

            unsigned long long a0 = *(const unsigned long long*)(zb + 0 * ZR_STRIDE + 2 * k2);
            unsigned long long a1 = *(const unsigned long long*)(zb + 1 * ZR_STRIDE + 2 * k2);
            unsigned long long a2 = *(const unsigned long long*)(zb + 2 * ZR_STRIDE + 2 * k2);
            unsigned long long a3 = *(const unsigned long long*)(zb + 3 * ZR_STRIDE + 2 * k2);

            ffma2(acc[0][0], a0, bf01.x); ffma2(acc[0][1], a0, bf01.y);
            ffma2(acc[0][2], a0, bf23.x); ffma2(acc[0][3], a0, bf23.y);
            ffma2(acc[0][4], a0, bs01.x); ffma2(acc[0][5], a0, bs01.y);
            ffma2(acc[0][6], a0, bs23.x); ffma2(acc[0][7], a0, bs23.y);

            ffma2(acc[1][0], a1, bf01.x); ffma2(acc[1][1], a1, bf01.y);
            ffma2(acc[1][2], a1, bf23.x); ffma2(acc[1][3], a1, bf23.y);
            ffma2(acc[1][4], a1, bs01.x); ffma2(acc[1][5], a1, bs01.y);
            ffma2(acc[1][6], a1, bs23.x); ffma2(acc[1][7], a1, bs23.y);

            ffma2(acc[2][0], a2, bf01.x); ffma2(acc[2][1], a2, bf01.y);
            ffma2(acc[2][2], a2, bf23.x); ffma2(acc[2][3], a2, bf23.y);
            ffma2(acc[2][4], a2, bs01.x); ffma2(acc[2][5], a2, bs01.y);
            ffma2(acc[2][6], a2, bs23.x); ffma2(acc[2][7], a2, bs23.y);

            ffma2(acc[3][0], a3, bf01.x); ffma2(acc[3][1], a3, bf01.y);
            ffma2(acc[3][2], a3, bf23.x); ffma2(acc[3][3], a3, bf23.y);
            ffma2(acc[3][4], a3, bs01.x); ffma2(acc[3][5], a3, bs01.y);
            ffma2(acc[3][6], a3, bs23.x); ffma2(acc[3][7], a3, bs23.y);
        }

        // epilogue: fold k-parity halves, gated activation, vectorized scatter
        #pragma unroll
        for (int i = 0; i < 4; i++) {
            int   r    = ty * 4 + i;
            int   dstn = sdstb[r];
            float dec  = sdecb[r];
            float m[4];
            #pragma unroll
            for (int j = 0; j < 4; j++) {
                float zf = lo32(acc[i][j])     + hi32(acc[i][j])     + sbias[cb + j];
                float zs = lo32(acc[i][j + 4]) + hi32(acc[i][j + 4]) + sbias[64 + cb + j];
                float sig = __fdividef(1.0f, 1.0f + __expf(-zf));
                float sp  = (zs > 15.0f) ? zs : log1pf(__expf(zs));
                m[j] = sig * sp * dec;
            }
            float* outp = atom_out + (size_t)dstn * F + cb;
            asm volatile("red.global.add.v4.f32 [%0], {%1, %2, %3, %4};"
                         :: "l"(outp), "f"(m[0]), "f"(m[1]), "f"(m[2]), "f"(m[3])
                         : "memory");
        }
        __syncthreads();
        buf ^= 1;
    }
}

// ---------------------------------------------------------------------------
// K2: edge-update MLP (unchanged from passing version). One warp per edge.
// ---------------------------------------------------------------------------
__global__ void __launch_bounds__(256, 2)
k2_edge(const float* __restrict__ atom_out,
        const int*   __restrict__ eidx,
        const float* __restrict__ efea,
        const float* __restrict__ w1,   // [14][192]
        const float* __restrict__ b1,   // [14]
        const float* __restrict__ w2,   // [64][14]
        const float* __restrict__ b2,   // [64]
        float* __restrict__ edge_out,
        int nwarps)
{
    __shared__ float s_w2t[HID * 64];
    __shared__ float s_b2[64];
    __shared__ float s_b1[16];

    const int tid  = threadIdx.x;
    const int lane = tid & 31;
    const int wid  = tid >> 5;

    for (int i = tid; i < HID * 64; i += 256) {
        int j = i / 64, o = i % 64;
        s_w2t[i] = w2[o * HID + j];
    }
    if (tid < 64) s_b2[tid] = b2[tid];
    if (tid < 16) s_b1[tid] = (tid < HID) ? b1[tid] : 0.0f;
    __syncthreads();

    float w1r[6][HID];
    #pragma unroll
    for (int t = 0; t < 6; t++)
        #pragma unroll
        for (int j = 0; j < HID; j++)
            w1r[t][j] = w1[j * ZD + (lane + 32 * t)];

    const int gw = blockIdx.x * 8 + wid;
    const unsigned full = 0xffffffffu;

    for (int e = gw; e < NE; e += nwarps) {
        int s = eidx[e];
        int d = eidx[NE + e];
        const float* rs = atom_out + (size_t)s * F;
        const float* rd = atom_out + (size_t)d * F;
        const float* re = efea + (size_t)e * F;

        float z[6];
        z[0] = rs[lane];      z[1] = rs[lane + 32];
        z[2] = rd[lane];      z[3] = rd[lane + 32];
        z[4] = re[lane];      z[5] = re[lane + 32];

        float ph[HID];
        #pragma unroll
        for (int j = 0; j < HID; j++) {
            float a = z[0] * w1r[0][j];
            a += z[1] * w1r[1][j];
            a += z[2] * w1r[2][j];
            a += z[3] * w1r[3][j];
            a += z[4] * w1r[4][j];
            a += z[5] * w1r[5][j];
            ph[j] = a;
        }
        #pragma unroll
        for (int j = 0; j < HID; j++) {
            #pragma unroll
            for (int off = 16; off > 0; off >>= 1)
                ph[j] += __shfl_xor_sync(full, ph[j], off);
        }
        float myh = ph[0];
        #pragma unroll
        for (int j = 1; j < HID; j++)
            if (lane == j) myh = ph[j];
        int bidx = lane < HID ? lane : 0;
        float x  = myh + s_b1[bidx];
        float hs = x * __fdividef(1.0f, 1.0f + __expf(-x));

        float a0 = s_b2[lane];
        float a1 = s_b2[lane + 32];
        #pragma unroll
        for (int j = 0; j < HID; j++) {
            float hj = __shfl_sync(full, hs, j);
            a0 += hj * s_w2t[j * 64 + lane];
            a1 += hj * s_w2t[j * 64 + lane + 32];
        }
        float o0 = a0 * __fdividef(1.0f, 1.0f + __expf(-a0));
        float o1 = a1 * __fdividef(1.0f, 1.0f + __expf(-a1));
        edge_out[(size_t)e * F + lane]      = o0;
        edge_out[(size_t)e * F + lane + 32] = o1;
    }
}

// ---------------------------------------------------------------------------
// Launch
// ---------------------------------------------------------------------------
extern "C" void kernel_launch(void* const* d_in, const int* in_sizes, int n_in,
                              void* d_out, int out_size)
{
    const float* atom  = (const float*)d_in[0];
    const int*   eidx  = (const int*)  d_in[1];
    const float* efea  = (const float*)d_in[2];
    const float* dist  = (const float*)d_in[4];
    const float* wf    = (const float*)d_in[6];
    const float* bf    = (const float*)d_in[7];
    const float* wss   = (const float*)d_in[8];
    const float* bs    = (const float*)d_in[9];
    const float* w1    = (const float*)d_in[10];
    const float* b1    = (const float*)d_in[11];
    const float* w2    = (const float*)d_in[12];
    const float* b2    = (const float*)d_in[13];

    float* atom_out = (float*)d_out;
    float* edge_out = atom_out + (size_t)NNODES * F;

    // K0: init atom_out + build interleaved combined weights
    k0_prep<<<(NNODES * F / 4 + 255) / 256, 256>>>(atom, wf, wss, atom_out);

    // K1: persistent message GEMM + scatter
    const int smem_k1 = (ZD * NT + 2 * MT * ZR_STRIDE + NT + 2 * MT) * 4
                        + 2 * MT * 4;   // weights + 2x z + bias + 2x dec + 2x dst
    cudaFuncSetAttribute(k1_msg, cudaFuncAttributeMaxDynamicSharedMemorySize, smem_k1);
    k1_msg<<<K1_GRID, 256, smem_k1>>>(atom, eidx, efea, dist, bf, bs, atom_out);

    // K2: edge MLP
    const int blocks = 296;
    const int nwarps = blocks * 8;
    k2_edge<<<blocks, 256>>>(atom_out, eidx, efea, w1, b1, w2, b2, edge_out, nwarps);
}

// round 3
// speedup vs baseline: 2.0787x; 2.0787x over previous
#include <cuda_runtime.h>
#include <math.h>

#define NE      800000
#define NNODES  50000
#define F       64
#define ZD      192
#define HID     14

// ---------------- device scratch (static, allowed) ----------------
__device__ float g_wab_t[64 * 256];          // k-major: [k][c] c: f_dst|s_dst|f_src|s_src
__device__ float g_we_t [64 * 128];          // k-major edge-part weights: f|s
__device__ float g_P    [NNODES * 256];      // per-node msg precompute (+bias in dst part)
__device__ float g_H    [NNODES * 32];       // per-node fc1 precompute: Ha(14,+b1)|pad|Hb(14)|pad

// ---------------------------------------------------------------------------
// K0a: atom_out = atom_fea
// ---------------------------------------------------------------------------
__global__ void k0_copy(const float* __restrict__ atom, float* __restrict__ atom_out)
{
    int i = blockIdx.x * blockDim.x + threadIdx.x;
    if (i < NNODES * F / 4)
        ((float4*)atom_out)[i] = ((const float4*)atom)[i];
}

// ---------------------------------------------------------------------------
// K0b: build k-major weight blocks
// ---------------------------------------------------------------------------
__global__ void k0_weights(const float* __restrict__ wf, const float* __restrict__ ws_)
{
    int i = blockIdx.x * blockDim.x + threadIdx.x;
    if (i < 64 * 256) {
        int k = i >> 8, c = i & 255;
        float v;
        if      (c < 64)  v = wf [c * ZD + k];              // f, dst slice
        else if (c < 128) v = ws_[(c - 64) * ZD + k];       // s, dst slice
        else if (c < 192) v = wf [(c - 128) * ZD + 64 + k]; // f, src slice
        else              v = ws_[(c - 192) * ZD + 64 + k]; // s, src slice
        g_wab_t[i] = v;
    }
    if (i < 64 * 128) {
        int k = i >> 7, c = i & 127;
        g_we_t[i] = (c < 64) ? wf[c * ZD + 128 + k] : ws_[(c - 64) * ZD + 128 + k];
    }
}

// ---------------------------------------------------------------------------
// K_node: P[n][256] = atom[n] @ g_wab_t  (+ bf/bs folded into dst halves)
// block = 64 nodes, 256 threads, thread = 4 rows x 16 cols
// ---------------------------------------------------------------------------
#define NBS 260   // Bs col stride
#define NAS 68    // As col stride
__global__ void __launch_bounds__(256)
k_node(const float* __restrict__ atom,
       const float* __restrict__ bf, const float* __restrict__ bs)
{
    extern __shared__ float sm[];
    float* Bs = sm;              // 64 x 260
    float* As = Bs + 64 * NBS;   // 64 x 68

    const int tid = threadIdx.x;
    const int n0  = blockIdx.x * 64;

    // stage B (g_wab_t) : 4096 float4
    {
        const float4* w4 = (const float4*)g_wab_t;
        #pragma unroll
        for (int it = 0; it < 16; it++) {
            int idx = tid + it * 256;        // < 4096
            int k = idx >> 6, c4 = idx & 63;
            *(float4*)&Bs[k * NBS + c4 * 4] = w4[idx];
        }
    }
    // stage A rows (guarded)
    #pragma unroll
    for (int it = 0; it < 4; it++) {
        int idx = tid + it * 256;            // < 1024
        int row = idx >> 4, k4 = idx & 15;
        float4 v = make_float4(0.f, 0.f, 0.f, 0.f);
        if (n0 + row < NNODES)
            v = ((const float4*)(atom + (size_t)(n0 + row) * F))[k4];
        *(float4*)&As[row * NAS + k4 * 4] = v;
    }
    __syncthreads();

    const int tx = tid & 15, ty = tid >> 4;
    const int c0 = tx * 16;
    float acc[4][16];
    #pragma unroll
    for (int i = 0; i < 4; i++)
        #pragma unroll
        for (int j = 0; j < 16; j++) acc[i][j] = 0.f;

    #pragma unroll 4
    for (int k = 0; k < 64; k++) {
        float4 b0 = *(const float4*)&Bs[k * NBS + c0];
        float4 b1 = *(const float4*)&Bs[k * NBS + c0 + 4];
        float4 b2 = *(const float4*)&Bs[k * NBS + c0 + 8];
        float4 b3 = *(const float4*)&Bs[k * NBS + c0 + 12];
        #pragma unroll
        for (int i = 0; i < 4; i++) {
            float a = As[(ty * 4 + i) * NAS + k];
            acc[i][0]  += a * b0.x; acc[i][1]  += a * b0.y; acc[i][2]  += a * b0.z; acc[i][3]  += a * b0.w;
            acc[i][4]  += a * b1.x; acc[i][5]  += a * b1.y; acc[i][6]  += a * b1.z; acc[i][7]  += a * b1.w;
            acc[i][8]  += a * b2.x; acc[i][9]  += a * b2.y; acc[i][10] += a * b2.z; acc[i][11] += a * b2.w;
            acc[i][12] += a * b3.x; acc[i][13] += a * b3.y; acc[i][14] += a * b3.z; acc[i][15] += a * b3.w;
        }
    }

    #pragma unroll
    for (int i = 0; i < 4; i++) {
        int n = n0 + ty * 4 + i;
        if (n >= NNODES) continue;
        float* outp = g_P + (size_t)n * 256 + c0;
        #pragma unroll
        for (int q = 0; q < 4; q++) {
            float4 v;
            float* a = &acc[i][q * 4];
            int cbase = c0 + q * 4;
            float bias[4];
            #pragma unroll
            for (int e = 0; e < 4; e++) {
                int c = cbase + e;
                bias[e] = (c < 64) ? bf[c] : (c < 128 ? bs[c - 64] : 0.f);
            }
            v.x = a[0] + bias[0]; v.y = a[1] + bias[1];
            v.z = a[2] + bias[2]; v.w = a[3] + bias[3];
            *(float4*)(outp + q * 4) = v;
        }
    }
}

// ---------------------------------------------------------------------------
// K_gemm: per tile of 128 edges: Me = efea_tile @ g_we_t  (128x128, K=64),
// epilogue: + P[dst](f,s) + P[src](f,s), gate, decay, red.v4 scatter.
// 512 threads: tx(16) x ty(32); thread = 4 edges x (4 f-cols + 4 s-cols)
// ---------------------------------------------------------------------------
#define GBS 132   // Bs stride
#define GAS 68    // As stride
__global__ void __launch_bounds__(512)
k_gemm(const float* __restrict__ efea,
       const int*   __restrict__ eidx,
       const float* __restrict__ dist,
       float* __restrict__ atom_out)
{
    extern __shared__ float sm[];
    float* Bs   = sm;                 // 64 x 132  = 8448
    float* As   = Bs + 64 * GBS;      // 128 x 68  = 8704
    float* sdec = As + 128 * GAS;     // 128
    int*   sdst = (int*)(sdec + 128); // 128
    int*   ssrc = sdst + 128;         // 128

    const int tid = threadIdx.x;
    const int e0  = blockIdx.x * 128;

    // stage B: 2048 float4
    {
        const float4* w4 = (const float4*)g_we_t;
        #pragma unroll
        for (int it = 0; it < 4; it++) {
            int idx = tid + it * 512;        // < 2048
            int k = idx >> 5, c4 = idx & 31;
            *(float4*)&Bs[k * GBS + c4 * 4] = w4[idx];
        }
    }
    // edge meta
    if (tid < 128) {
        int e = e0 + tid;
        ssrc[tid] = eidx[e];
        sdst[tid] = eidx[NE + e];
        float d = dist[e];
        sdec[tid] = __expf(-d * d * (1.0f / 18.0f));
    }
    // stage A: 2048 float4, fully coalesced
    {
        const float4* a4 = (const float4*)(efea + (size_t)e0 * F);
        #pragma unroll
        for (int it = 0; it < 4; it++) {
            int idx = tid + it * 512;        // < 2048
            int row = idx >> 4, k4 = idx & 15;
            *(float4*)&As[row * GAS + k4 * 4] = a4[idx];
        }
    }
    __syncthreads();

    const int tx = tid & 15, ty = tid >> 4;   // ty 0..31
    const int cb = tx * 4;
    const int r0 = ty * 4;

    float acc[4][8];
    #pragma unroll
    for (int i = 0; i < 4; i++)
        #pragma unroll
        for (int j = 0; j < 8; j++) acc[i][j] = 0.f;

    #pragma unroll 8
    for (int k = 0; k < 64; k++) {
        float4 bF = *(const float4*)&Bs[k * GBS + cb];
        float4 bS = *(const float4*)&Bs[k * GBS + 64 + cb];
        #pragma unroll
        for (int i = 0; i < 4; i++) {
            float a = As[(r0 + i) * GAS + k];
            acc[i][0] += a * bF.x; acc[i][1] += a * bF.y;
            acc[i][2] += a * bF.z; acc[i][3] += a * bF.w;
            acc[i][4] += a * bS.x; acc[i][5] += a * bS.y;
            acc[i][6] += a * bS.z; acc[i][7] += a * bS.w;
        }
    }

    // epilogue
    #pragma unroll
    for (int i = 0; i < 4; i++) {
        int r   = r0 + i;
        int dst = sdst[r];
        int src = ssrc[r];
        float dec = sdec[r];
        const float* pd = g_P + (size_t)dst * 256;
        const float* ps = g_P + (size_t)src * 256;
        float4 pfd = *(const float4*)(pd + cb);          // f dst (+bf)
        float4 psd = *(const float4*)(pd + 64 + cb);     // s dst (+bs)
        float4 pfs = *(const float4*)(ps + 128 + cb);    // f src
        float4 pss = *(const float4*)(ps + 192 + cb);    // s src
        float zf[4], zs[4], m[4];
        zf[0] = acc[i][0] + pfd.x + pfs.x;  zs[0] = acc[i][4] + psd.x + pss.x;
        zf[1] = acc[i][1] + pfd.y + pfs.y;  zs[1] = acc[i][5] + psd.y + pss.y;
        zf[2] = acc[i][2] + pfd.z + pfs.z;  zs[2] = acc[i][6] + psd.z + pss.z;
        zf[3] = acc[i][3] + pfd.w + pfs.w;  zs[3] = acc[i][7] + psd.w + pss.w;
        #pragma unroll
        for (int j = 0; j < 4; j++) {
            float sig = __fdividef(1.0f, 1.0f + __expf(-zf[j]));
            float sp  = (zs[j] > 15.0f) ? zs[j] : log1pf(__expf(zs[j]));
            m[j] = sig * sp * dec;
        }
        float* outp = atom_out + (size_t)dst * F + cb;
        asm volatile("red.global.add.v4.f32 [%0], {%1, %2, %3, %4};"
                     :: "l"(outp), "f"(m[0]), "f"(m[1]), "f"(m[2]), "f"(m[3])
                     : "memory");
    }
}

// ---------------------------------------------------------------------------
// K3: H[n] = [ atom_out[n]@W1a^T + b1 (14, pad 16) | atom_out[n]@W1b^T (14, pad 16) ]
// block = 64 nodes, 256 threads
// ---------------------------------------------------------------------------
__global__ void __launch_bounds__(256)
k3_nodeH(const float* __restrict__ atom_out,
         const float* __restrict__ w1, const float* __restrict__ b1)
{
    __shared__ float rows[64 * NAS];   // 64 x 68
    __shared__ float sW1[64 * 32];     // [k][j]  j<14: W1a, 16<=j<30: W1b

    const int tid = threadIdx.x;
    const int n0  = blockIdx.x * 64;

    #pragma unroll
    for (int it = 0; it < 8; it++) {
        int idx = tid + it * 256;          // < 2048
        int k = idx >> 5, j = idx & 31;
        float v = 0.f;
        if (j < HID)                 v = w1[j * ZD + k];
        else if (j >= 16 && j < 30)  v = w1[(j - 16) * ZD + 64 + k];
        sW1[idx] = v;
    }
    #pragma unroll
    for (int it = 0; it < 4; it++) {
        int idx = tid + it * 256;          // < 1024
        int row = idx >> 4, k4 = idx & 15;
        float4 v = make_float4(0.f, 0.f, 0.f, 0.f);
        if (n0 + row < NNODES)
            v = ((const float4*)(atom_out + (size_t)(n0 + row) * F))[k4];
        *(float4*)&rows[row * NAS + k4 * 4] = v;
    }
    __syncthreads();

    const int j   = tid & 31;
    const int nl0 = tid >> 5;
    float bias = (j < HID) ? b1[j] : 0.f;

    #pragma unroll
    for (int it = 0; it < 8; it++) {
        int nl = nl0 + it * 8;
        int n  = n0 + nl;
        float acc = 0.f;
        #pragma unroll 8
        for (int k = 0; k < 64; k++)
            acc += rows[nl * NAS + k] * sW1[k * 32 + j];
        if (j < HID) acc += bias;
        if (n < NNODES) g_H[(size_t)n * 32 + j] = acc;
    }
}

// ---------------------------------------------------------------------------
// K2: edge MLP. warp per edge. fc1 = Ha[src] + Hb[dst] + efea-part (shfl-reduced)
// ---------------------------------------------------------------------------
__global__ void __launch_bounds__(256, 2)
k2_edge(const int*   __restrict__ eidx,
        const float* __restrict__ efea,
        const float* __restrict__ w1,   // [14][192]
        const float* __restrict__ w2,   // [64][14]
        const float* __restrict__ b2,   // [64]
        float* __restrict__ edge_out,
        int nwarps)
{
    __shared__ float s_w2t[HID * 64];
    __shared__ float s_b2[64];

    const int tid  = threadIdx.x;
    const int lane = tid & 31;
    const int wid  = tid >> 5;

    for (int i = tid; i < HID * 64; i += 256) {
        int j = i / 64, o = i % 64;
        s_w2t[i] = w2[o * HID + j];
    }
    if (tid < 64) s_b2[tid] = b2[tid];
    __syncthreads();

    // edge-part fc1 weights, register resident: k = 128 + lane + 32t
    float w1c[2][HID];
    #pragma unroll
    for (int t = 0; t < 2; t++)
        #pragma unroll
        for (int j = 0; j < HID; j++)
            w1c[t][j] = w1[j * ZD + 128 + lane + 32 * t];

    const int gw = blockIdx.x * 8 + wid;
    const unsigned full = 0xffffffffu;

    for (int e = gw; e < NE; e += nwarps) {
        int s = eidx[e];
        int d = eidx[NE + e];
        const float* re = efea + (size_t)e * F;
        float z4 = re[lane];
        float z5 = re[lane + 32];

        float ph[HID];
        #pragma unroll
        for (int j = 0; j < HID; j++)
            ph[j] = z4 * w1c[0][j] + z5 * w1c[1][j];
        #pragma unroll
        for (int j = 0; j < HID; j++) {
            #pragma unroll
            for (int off = 16; off > 0; off >>= 1)
                ph[j] += __shfl_xor_sync(full, ph[j], off);
        }
        float myh = ph[0];
        #pragma unroll
        for (int j = 1; j < HID; j++)
            if (lane == j) myh = ph[j];
        float hs = 0.f;
        if (lane < HID) {
            float x = myh + g_H[(size_t)s * 32 + lane]          // Ha (+b1 folded)
                          + g_H[(size_t)d * 32 + 16 + lane];    // Hb
            hs = x * __fdividef(1.0f, 1.0f + __expf(-x));
        }

        float a0 = s_b2[lane];
        float a1 = s_b2[lane + 32];
        #pragma unroll
        for (int j = 0; j < HID; j++) {
            float hj = __shfl_sync(full, hs, j);
            a0 += hj * s_w2t[j * 64 + lane];
            a1 += hj * s_w2t[j * 64 + lane + 32];
        }
        float o0 = a0 * __fdividef(1.0f, 1.0f + __expf(-a0));
        float o1 = a1 * __fdividef(1.0f, 1.0f + __expf(-a1));
        edge_out[(size_t)e * F + lane]      = o0;
        edge_out[(size_t)e * F + lane + 32] = o1;
    }
}

// ---------------------------------------------------------------------------
// Launch. Inputs: 0 atom_fea, 1 edge_idx, 2 edge_fea, 3 batch, 4 distance,
// 5 edge_vec, 6 lin_f_w, 7 lin_f_b, 8 lin_s_w, 9 lin_s_b, 10 fc1_w, 11 fc1_b,
// 12 fc2_w, 13 fc2_b. Output: atom_out[50000*64] ++ edge_out[800000*64].
// ---------------------------------------------------------------------------
extern "C" void kernel_launch(void* const* d_in, const int* in_sizes, int n_in,
                              void* d_out, int out_size)
{
    const float* atom  = (const float*)d_in[0];
    const int*   eidx  = (const int*)  d_in[1];
    const float* efea  = (const float*)d_in[2];
    const float* dist  = (const float*)d_in[4];
    const float* wf    = (const float*)d_in[6];
    const float* bf    = (const float*)d_in[7];
    const float* wss   = (const float*)d_in[8];
    const float* bs    = (const float*)d_in[9];
    const float* w1    = (const float*)d_in[10];
    const float* b1    = (const float*)d_in[11];
    const float* w2    = (const float*)d_in[12];
    const float* b2    = (const float*)d_in[13];

    float* atom_out = (float*)d_out;
    float* edge_out = atom_out + (size_t)NNODES * F;

    // 1) copy residual base
    k0_copy<<<(NNODES * F / 4 + 255) / 256, 256>>>(atom, atom_out);
    // 2) transpose/stage weights
    k0_weights<<<(64 * 256 + 255) / 256, 256>>>(wf, wss);
    // 3) per-node msg precompute P
    const int smem_node = (64 * NBS + 64 * NAS) * 4;
    cudaFuncSetAttribute(k_node, cudaFuncAttributeMaxDynamicSharedMemorySize, smem_node);
    k_node<<<(NNODES + 63) / 64, 256, smem_node>>>(atom, bf, bs);
    // 4) streaming edge GEMM + gated scatter
    const int smem_gemm = (64 * GBS + 128 * GAS + 128) * 4 + 2 * 128 * 4;
    cudaFuncSetAttribute(k_gemm, cudaFuncAttributeMaxDynamicSharedMemorySize, smem_gemm);
    k_gemm<<<NE / 128, 512, smem_gemm>>>(efea, eidx, dist, atom_out);
    // 5) per-node fc1 precompute H (on final atom_out)
    k3_nodeH<<<(NNODES + 63) / 64, 256>>>(atom_out, w1, b1);
    // 6) edge MLP
    const int blocks = 296;
    k2_edge<<<blocks, 256>>>(eidx, efea, w1, w2, b2, edge_out, blocks * 8);
}

// round 6
// speedup vs baseline: 3.2938x; 1.5846x over previous
#include <cuda_runtime.h>
#include <cuda_bf16.h>
#include <math.h>

#define NE      800000
#define NNODES  50000
#define F       64
#define ZD      192
#define HID     14

// ---------------- device scratch ----------------
__device__ float g_wab_t[64 * 256];            // k-major node-part weights (permuted cols)
__device__ float g_P    [NNODES * 256];        // per-node msg precompute (interleaved layout)
__device__ float g_H    [NNODES * 32];         // per-node fc1 precompute
__device__ __align__(16) __nv_bfloat16 g_wb_hi[128 * 64];  // edge-part W, [n][k], col-interleaved
__device__ __align__(16) __nv_bfloat16 g_wb_lo[128 * 64];  // lo residual

// ---------------------------------------------------------------------------
__device__ __forceinline__ unsigned pack_bf(__nv_bfloat16 a, __nv_bfloat16 b) {
    return (unsigned)__bfloat16_as_ushort(a) | ((unsigned)__bfloat16_as_ushort(b) << 16);
}
__device__ __forceinline__ void mma16816(float* c, const unsigned* a,
                                         unsigned b0, unsigned b1) {
    asm volatile(
        "mma.sync.aligned.m16n8k16.row.col.f32.bf16.bf16.f32 "
        "{%0,%1,%2,%3}, {%4,%5,%6,%7}, {%8,%9}, {%0,%1,%2,%3};"
        : "+f"(c[0]), "+f"(c[1]), "+f"(c[2]), "+f"(c[3])
        : "r"(a[0]), "r"(a[1]), "r"(a[2]), "r"(a[3]), "r"(b0), "r"(b1));
}

// ---------------------------------------------------------------------------
// K0a: atom_out = atom_fea
// ---------------------------------------------------------------------------
__global__ void k0_copy(const float* __restrict__ atom, float* __restrict__ atom_out)
{
    int i = blockIdx.x * blockDim.x + threadIdx.x;
    if (i < NNODES * F / 4)
        ((float4*)atom_out)[i] = ((const float4*)atom)[i];
}

// ---------------------------------------------------------------------------
// K0b: build node-part k-major weights (permuted) + edge-part bf16 hi/lo.
// Column permutation everywhere: pairs (f_j, s_j) interleaved.
//   g_wab_t cols: c<128: (c>>1)=j, c&1 ? s_dst : f_dst; c>=128: src slice.
//   g_wb cols:    n: (n>>1)=j, n&1 ? s_edge : f_edge.
// ---------------------------------------------------------------------------
__global__ void k0_weights(const float* __restrict__ wf, const float* __restrict__ ws_)
{
    int i = blockIdx.x * blockDim.x + threadIdx.x;
    if (i < 64 * 256) {
        int k = i >> 8, c = i & 255;
        int cc = c & 127;
        int j = cc >> 1;
        const float* base = (cc & 1) ? ws_ : wf;
        int koff = (c < 128) ? 0 : 64;
        g_wab_t[i] = base[j * ZD + koff + k];
    }
    if (i < 128 * 64) {
        int n = i >> 6, k = i & 63;
        int j = n >> 1;
        const float* base = (n & 1) ? ws_ : wf;
        float v = base[j * ZD + 128 + k];
        __nv_bfloat16 hi = __float2bfloat16(v);
        __nv_bfloat16 lo = __float2bfloat16(v - __bfloat162float(hi));
        g_wb_hi[i] = hi;
        g_wb_lo[i] = lo;
    }
}

// ---------------------------------------------------------------------------
// K_node: P[n][256] = atom[n] @ g_wab_t, biases folded:
//   c<128: + (c&1 ? bs[c>>1] : bf[c>>1]); c>=128: +0
// ---------------------------------------------------------------------------
#define NBS 260
#define NAS 68
__global__ void __launch_bounds__(256)
k_node(const float* __restrict__ atom,
       const float* __restrict__ bf, const float* __restrict__ bs)
{
    extern __shared__ float sm[];
    float* Bs = sm;
    float* As = Bs + 64 * NBS;

    const int tid = threadIdx.x;
    const int n0  = blockIdx.x * 64;

    {
        const float4* w4 = (const float4*)g_wab_t;
        #pragma unroll
        for (int it = 0; it < 16; it++) {
            int idx = tid + it * 256;
            int k = idx >> 6, c4 = idx & 63;
            *(float4*)&Bs[k * NBS + c4 * 4] = w4[idx];
        }
    }
    #pragma unroll
    for (int it = 0; it < 4; it++) {
        int idx = tid + it * 256;
        int row = idx >> 4, k4 = idx & 15;
        float4 v = make_float4(0.f, 0.f, 0.f, 0.f);
        if (n0 + row < NNODES)
            v = ((const float4*)(atom + (size_t)(n0 + row) * F))[k4];
        *(float4*)&As[row * NAS + k4 * 4] = v;
    }
    __syncthreads();

    const int tx = tid & 15, ty = tid >> 4;
    const int c0 = tx * 16;
    float acc[4][16];
    #pragma unroll
    for (int i = 0; i < 4; i++)
        #pragma unroll
        for (int j = 0; j < 16; j++) acc[i][j] = 0.f;

    #pragma unroll 4
    for (int k = 0; k < 64; k++) {
        float4 b0 = *(const float4*)&Bs[k * NBS + c0];
        float4 b1 = *(const float4*)&Bs[k * NBS + c0 + 4];
        float4 b2 = *(const float4*)&Bs[k * NBS + c0 + 8];
        float4 b3 = *(const float4*)&Bs[k * NBS + c0 + 12];
        #pragma unroll
        for (int i = 0; i < 4; i++) {
            float a = As[(ty * 4 + i) * NAS + k];
            acc[i][0]  += a * b0.x; acc[i][1]  += a * b0.y; acc[i][2]  += a * b0.z; acc[i][3]  += a * b0.w;
            acc[i][4]  += a * b1.x; acc[i][5]  += a * b1.y; acc[i][6]  += a * b1.z; acc[i][7]  += a * b1.w;
            acc[i][8]  += a * b2.x; acc[i][9]  += a * b2.y; acc[i][10] += a * b2.z; acc[i][11] += a * b2.w;
            acc[i][12] += a * b3.x; acc[i][13] += a * b3.y; acc[i][14] += a * b3.z; acc[i][15] += a * b3.w;
        }
    }

    #pragma unroll
    for (int i = 0; i < 4; i++) {
        int n = n0 + ty * 4 + i;
        if (n >= NNODES) continue;
        float* outp = g_P + (size_t)n * 256 + c0;
        #pragma unroll
        for (int q = 0; q < 4; q++) {
            int cbase = c0 + q * 4;
            float bias[4];
            #pragma unroll
            for (int e = 0; e < 4; e++) {
                int c = cbase + e;
                bias[e] = (c < 128) ? ((c & 1) ? bs[c >> 1] : bf[c >> 1]) : 0.f;
            }
            float4 v;
            float* a = &acc[i][q * 4];
            v.x = a[0] + bias[0]; v.y = a[1] + bias[1];
            v.z = a[2] + bias[2]; v.w = a[3] + bias[3];
            *(float4*)(outp + q * 4) = v;
        }
    }
}

// ---------------------------------------------------------------------------
// K_gemm_mma: HMMA bf16 3-split edge GEMM + gated scatter.
// Tile: 128 edges x 128 cols (f/s interleaved), K=64.
// 8 warps = 2(m) x 4(n); warp: 4 m16 tiles x 4 n8 tiles.
// D = Ah Bh + Ah Bl + Al Bh (fp32 regs). Epilogue: +P[dst]/P[src] (float2
// pairs), sigmoid*softplus*decay, scalar red.global.add.
// ---------------------------------------------------------------------------
#define SMA 72   // bf16 row stride (144B; 36 words -> conflict-free frag loads)
__global__ void __launch_bounds__(256, 2)
k_gemm_mma(const float* __restrict__ efea,
           const int*   __restrict__ eidx,
           const float* __restrict__ dist,
           float* __restrict__ atom_out)
{
    extern __shared__ char smc[];
    char* Ah = smc;
    char* Al = Ah + 128 * SMA * 2;
    char* Bh = Al + 128 * SMA * 2;
    char* Bl = Bh + 128 * SMA * 2;
    float* sdec = (float*)(Bl + 128 * SMA * 2);
    int*   sdst = (int*)(sdec + 128);
    int*   ssrc = sdst + 128;

    const int tid  = threadIdx.x;
    const int lane = tid & 31;
    const int wid  = tid >> 5;
    const int e0   = blockIdx.x * 128;

    // stage B (hi/lo): 1024 uint4 each
    {
        const uint4* gh = (const uint4*)g_wb_hi;
        const uint4* gl = (const uint4*)g_wb_lo;
        #pragma unroll
        for (int it = 0; it < 4; it++) {
            int idx = tid + it * 256;        // < 1024
            int n = idx >> 3, k8 = idx & 7;
            *(uint4*)(Bh + n * 144 + k8 * 16) = gh[idx];
            *(uint4*)(Bl + n * 144 + k8 * 16) = gl[idx];
        }
    }
    // edge meta
    if (tid < 128) {
        int e = e0 + tid;
        ssrc[tid] = eidx[e];
        sdst[tid] = eidx[NE + e];
        float d = dist[e];
        sdec[tid] = __expf(-d * d * (1.0f / 18.0f));
    }
    // stage A: split f32 -> hi/lo bf16
    {
        const float4* a4 = (const float4*)(efea + (size_t)e0 * F);
        #pragma unroll
        for (int it = 0; it < 8; it++) {
            int idx = tid + it * 256;        // < 2048
            int row = idx >> 4, k4 = idx & 15;
            float4 v = a4[idx];
            __nv_bfloat16 h0 = __float2bfloat16(v.x);
            __nv_bfloat16 h1 = __float2bfloat16(v.y);
            __nv_bfloat16 h2 = __float2bfloat16(v.z);
            __nv_bfloat16 h3 = __float2bfloat16(v.w);
            __nv_bfloat16 l0 = __float2bfloat16(v.x - __bfloat162float(h0));
            __nv_bfloat16 l1 = __float2bfloat16(v.y - __bfloat162float(h1));
            __nv_bfloat16 l2 = __float2bfloat16(v.z - __bfloat162float(h2));
            __nv_bfloat16 l3 = __float2bfloat16(v.w - __bfloat162float(h3));
            *(uint2*)(Ah + row * 144 + k4 * 8) = make_uint2(pack_bf(h0, h1), pack_bf(h2, h3));
            *(uint2*)(Al + row * 144 + k4 * 8) = make_uint2(pack_bf(l0, l1), pack_bf(l2, l3));
        }
    }
    __syncthreads();

    const int g  = lane >> 2;
    const int t  = lane & 3;
    const int wm = wid >> 2;          // 0..1
    const int wn = wid & 3;           // 0..3
    const int mrow = wm * 64;
    const int ncol = wn * 32;

    float acc[4][4][4];
    #pragma unroll
    for (int mt = 0; mt < 4; mt++)
        #pragma unroll
        for (int nt = 0; nt < 4; nt++)
            #pragma unroll
            for (int q = 0; q < 4; q++) acc[mt][nt][q] = 0.f;

    #pragma unroll
    for (int s = 0; s < 4; s++) {
        const int k0 = s * 16;
        unsigned ahf[4][4], alf[4][4];
        #pragma unroll
        for (int mt = 0; mt < 4; mt++) {
            int r0 = mrow + mt * 16 + g;
            int off0 = (r0 * SMA + k0 + 2 * t) * 2;
            int off1 = ((r0 + 8) * SMA + k0 + 2 * t) * 2;
            ahf[mt][0] = *(const unsigned*)(Ah + off0);
            ahf[mt][1] = *(const unsigned*)(Ah + off1);
            ahf[mt][2] = *(const unsigned*)(Ah + off0 + 16);
            ahf[mt][3] = *(const unsigned*)(Ah + off1 + 16);
            alf[mt][0] = *(const unsigned*)(Al + off0);
            alf[mt][1] = *(const unsigned*)(Al + off1);
            alf[mt][2] = *(const unsigned*)(Al + off0 + 16);
            alf[mt][3] = *(const unsigned*)(Al + off1 + 16);
        }
        #pragma unroll
        for (int nt = 0; nt < 4; nt++) {
            int n = ncol + nt * 8 + g;
            int boff = (n * SMA + k0 + 2 * t) * 2;
            unsigned bh0 = *(const unsigned*)(Bh + boff);
            unsigned bh1 = *(const unsigned*)(Bh + boff + 16);
            unsigned bl0 = *(const unsigned*)(Bl + boff);
            unsigned bl1 = *(const unsigned*)(Bl + boff + 16);
            #pragma unroll
            for (int mt = 0; mt < 4; mt++) {
                mma16816(acc[mt][nt], ahf[mt], bh0, bh1);
                mma16816(acc[mt][nt], ahf[mt], bl0, bl1);
                mma16816(acc[mt][nt], alf[mt], bh0, bh1);
            }
        }
    }

    // epilogue: thread owns rows {mrow+mt*16+g, +8}, col pairs (2j, 2j+1)
    #pragma unroll
    for (int mt = 0; mt < 4; mt++) {
        #pragma unroll
        for (int half = 0; half < 2; half++) {
            int r    = mrow + mt * 16 + g + half * 8;
            int dstn = sdst[r];
            int srcn = ssrc[r];
            float dec = sdec[r];
            const float* pd = g_P + (size_t)dstn * 256;
            const float* ps = g_P + (size_t)srcn * 256 + 128;
            float* orow = atom_out + (size_t)dstn * F;
            #pragma unroll
            for (int nt = 0; nt < 4; nt++) {
                int c0 = ncol + nt * 8 + 2 * t;
                float2 d2 = *(const float2*)(pd + c0);
                float2 s2 = *(const float2*)(ps + c0);
                float zf = acc[mt][nt][half * 2 + 0] + d2.x + s2.x;
                float zs = acc[mt][nt][half * 2 + 1] + d2.y + s2.y;
                float sig = __fdividef(1.0f, 1.0f + __expf(-zf));
                float sp  = (zs > 15.0f) ? zs : log1pf(__expf(zs));
                float m = sig * sp * dec;
                asm volatile("red.global.add.f32 [%0], %1;"
                             :: "l"(orow + (c0 >> 1)), "f"(m) : "memory");
            }
        }
    }
}

// ---------------------------------------------------------------------------
// K3: H[n] = [ atom_out[n]@W1a^T + b1 (14, pad16) | atom_out[n]@W1b^T (14, pad16) ]
// ---------------------------------------------------------------------------
__global__ void __launch_bounds__(256)
k3_nodeH(const float* __restrict__ atom_out,
         const float* __restrict__ w1, const float* __restrict__ b1)
{
    __shared__ float rows[64 * NAS];
    __shared__ float sW1[64 * 32];

    const int tid = threadIdx.x;
    const int n0  = blockIdx.x * 64;

    #pragma unroll
    for (int it = 0; it < 8; it++) {
        int idx = tid + it * 256;
        int k = idx >> 5, j = idx & 31;
        float v = 0.f;
        if (j < HID)                 v = w1[j * ZD + k];
        else if (j >= 16 && j < 30)  v = w1[(j - 16) * ZD + 64 + k];
        sW1[idx] = v;
    }
    #pragma unroll
    for (int it = 0; it < 4; it++) {
        int idx = tid + it * 256;
        int row = idx >> 4, k4 = idx & 15;
        float4 v = make_float4(0.f, 0.f, 0.f, 0.f);
        if (n0 + row < NNODES)
            v = ((const float4*)(atom_out + (size_t)(n0 + row) * F))[k4];
        *(float4*)&rows[row * NAS + k4 * 4] = v;
    }
    __syncthreads();

    const int j   = tid & 31;
    const int nl0 = tid >> 5;
    float bias = (j < HID) ? b1[j] : 0.f;

    #pragma unroll
    for (int it = 0; it < 8; it++) {
        int nl = nl0 + it * 8;
        int n  = n0 + nl;
        float acc = 0.f;
        #pragma unroll 8
        for (int k = 0; k < 64; k++)
            acc += rows[nl * NAS + k] * sW1[k * 32 + j];
        if (j < HID) acc += bias;
        if (n < NNODES) g_H[(size_t)n * 32 + j] = acc;
    }
}

// ---------------------------------------------------------------------------
// K2: edge MLP, thread-per-edge register GEMM.
// ---------------------------------------------------------------------------
#define K2S 133
__global__ void __launch_bounds__(128)
k2_edge(const int*   __restrict__ eidx,
        const float* __restrict__ efea,
        const float* __restrict__ w1,   // [14][192]
        const float* __restrict__ w2,   // [64][14]
        const float* __restrict__ b2,   // [64]
        float* __restrict__ edge_out)
{
    __shared__ float sA [64 * K2S];
    __shared__ float sW1[64 * 16];
    __shared__ float sW2[14 * 64];
    __shared__ float sB2[64];

    const int tid = threadIdx.x;
    const int e0  = blockIdx.x * 128;

    for (int i = tid; i < 64 * 16; i += 128) {
        int k = i >> 4, j = i & 15;
        sW1[i] = (j < HID) ? w1[j * ZD + 128 + k] : 0.f;
    }
    for (int i = tid; i < HID * 64; i += 128) {
        int j = i >> 6, o = i & 63;
        sW2[i] = w2[o * HID + j];
    }
    if (tid < 64) sB2[tid] = b2[tid];

    {
        const float4* a4 = (const float4*)(efea + (size_t)e0 * F);
        #pragma unroll
        for (int it = 0; it < 16; it++) {
            int idx = tid + it * 128;
            int row = idx >> 4, k4 = idx & 15;
            float4 v = a4[idx];
            sA[(k4 * 4 + 0) * K2S + row] = v.x;
            sA[(k4 * 4 + 1) * K2S + row] = v.y;
            sA[(k4 * 4 + 2) * K2S + row] = v.z;
            sA[(k4 * 4 + 3) * K2S + row] = v.w;
        }
    }
    __syncthreads();

    const int el = tid;
    const int e  = e0 + el;
    const int s  = eidx[e];
    const int d  = eidx[NE + e];

    float ph[16];
    #pragma unroll
    for (int j = 0; j < 16; j++) ph[j] = 0.f;
    #pragma unroll
    for (int kq = 0; kq < 4; kq++) {
        float a[16];
        #pragma unroll
        for (int i = 0; i < 16; i++)
            a[i] = sA[(kq * 16 + i) * K2S + el];
        #pragma unroll
        for (int i = 0; i < 16; i++) {
            float av = a[i];
            const float* wr = &sW1[(kq * 16 + i) * 16];
            float4 b0 = *(const float4*)(wr);
            float4 b1 = *(const float4*)(wr + 4);
            float4 b2v = *(const float4*)(wr + 8);
            float4 b3v = *(const float4*)(wr + 12);
            ph[0]  += av * b0.x;  ph[1]  += av * b0.y;  ph[2]  += av * b0.z;  ph[3]  += av * b0.w;
            ph[4]  += av * b1.x;  ph[5]  += av * b1.y;  ph[6]  += av * b1.z;  ph[7]  += av * b1.w;
            ph[8]  += av * b2v.x; ph[9]  += av * b2v.y; ph[10] += av * b2v.z; ph[11] += av * b2v.w;
            ph[12] += av * b3v.x; ph[13] += av * b3v.y; ph[14] += av * b3v.z; ph[15] += av * b3v.w;
        }
    }

    float hav[16], hbv[16];
    {
        const float4* ga = (const float4*)(g_H + (size_t)s * 32);
        const float4* gb = (const float4*)(g_H + (size_t)d * 32 + 16);
        *(float4*)&hav[0]  = ga[0]; *(float4*)&hav[4]  = ga[1];
        *(float4*)&hav[8]  = ga[2]; *(float4*)&hav[12] = ga[3];
        *(float4*)&hbv[0]  = gb[0]; *(float4*)&hbv[4]  = gb[1];
        *(float4*)&hbv[8]  = gb[2]; *(float4*)&hbv[12] = gb[3];
    }
    float h[HID];
    #pragma unroll
    for (int j = 0; j < HID; j++) {
        float x = ph[j] + hav[j] + hbv[j];
        h[j] = x * __fdividef(1.0f, 1.0f + __expf(-x));
    }

    float* orow = edge_out + (size_t)e * F;
    #pragma unroll
    for (int oq = 0; oq < 4; oq++) {
        float acc[16];
        #pragma unroll
        for (int tq = 0; tq < 16; tq++) acc[tq] = sB2[oq * 16 + tq];
        #pragma unroll
        for (int j = 0; j < HID; j++) {
            float hj = h[j];
            const float* wr = &sW2[j * 64 + oq * 16];
            float4 w0 = *(const float4*)(wr);
            float4 w1v = *(const float4*)(wr + 4);
            float4 w2v = *(const float4*)(wr + 8);
            float4 w3v = *(const float4*)(wr + 12);
            acc[0]  += hj * w0.x;  acc[1]  += hj * w0.y;  acc[2]  += hj * w0.z;  acc[3]  += hj * w0.w;
            acc[4]  += hj * w1v.x; acc[5]  += hj * w1v.y; acc[6]  += hj * w1v.z; acc[7]  += hj * w1v.w;
            acc[8]  += hj * w2v.x; acc[9]  += hj * w2v.y; acc[10] += hj * w2v.z; acc[11] += hj * w2v.w;
            acc[12] += hj * w3v.x; acc[13] += hj * w3v.y; acc[14] += hj * w3v.z; acc[15] += hj * w3v.w;
        }
        #pragma unroll
        for (int t4 = 0; t4 < 4; t4++) {
            float4 o;
            float v0 = acc[t4*4+0], v1 = acc[t4*4+1], v2 = acc[t4*4+2], v3 = acc[t4*4+3];
            o.x = v0 * __fdividef(1.0f, 1.0f + __expf(-v0));
            o.y = v1 * __fdividef(1.0f, 1.0f + __expf(-v1));
            o.z = v2 * __fdividef(1.0f, 1.0f + __expf(-v2));
            o.w = v3 * __fdividef(1.0f, 1.0f + __expf(-v3));
            *(float4*)(orow + oq * 16 + t4 * 4) = o;
        }
    }
}

// ---------------------------------------------------------------------------
// Launch. Inputs: 0 atom_fea, 1 edge_idx, 2 edge_fea, 3 batch, 4 distance,
// 5 edge_vec, 6 lin_f_w, 7 lin_f_b, 8 lin_s_w, 9 lin_s_b, 10 fc1_w, 11 fc1_b,
// 12 fc2_w, 13 fc2_b. Output: atom_out[50000*64] ++ edge_out[800000*64].
// ---------------------------------------------------------------------------
extern "C" void kernel_launch(void* const* d_in, const int* in_sizes, int n_in,
                              void* d_out, int out_size)
{
    const float* atom  = (const float*)d_in[0];
    const int*   eidx  = (const int*)  d_in[1];
    const float* efea  = (const float*)d_in[2];
    const float* dist  = (const float*)d_in[4];
    const float* wf    = (const float*)d_in[6];
    const float* bf    = (const float*)d_in[7];
    const float* wss   = (const float*)d_in[8];
    const float* bs    = (const float*)d_in[9];
    const float* w1    = (const float*)d_in[10];
    const float* b1    = (const float*)d_in[11];
    const float* w2    = (const float*)d_in[12];
    const float* b2    = (const float*)d_in[13];

    float* atom_out = (float*)d_out;
    float* edge_out = atom_out + (size_t)NNODES * F;

    k0_copy<<<(NNODES * F / 4 + 255) / 256, 256>>>(atom, atom_out);
    k0_weights<<<64, 256>>>(wf, wss);

    const int smem_node = (64 * NBS + 64 * NAS) * 4;
    cudaFuncSetAttribute(k_node, cudaFuncAttributeMaxDynamicSharedMemorySize, smem_node);
    k_node<<<(NNODES + 63) / 64, 256, smem_node>>>(atom, bf, bs);

    const int smem_mma = 4 * 128 * SMA * 2 + 128 * 4 * 3;   // 75264
    cudaFuncSetAttribute(k_gemm_mma, cudaFuncAttributeMaxDynamicSharedMemorySize, smem_mma);
    k_gemm_mma<<<NE / 128, 256, smem_mma>>>(efea, eidx, dist, atom_out);

    k3_nodeH<<<(NNODES + 63) / 64, 256>>>(atom_out, w1, b1);

    k2_edge<<<NE / 128, 128>>>(eidx, efea, w1, w2, b2, edge_out);
}